// round 14
// baseline (speedup 1.0000x reference)
#include <cuda_runtime.h>

typedef unsigned long long u64;
typedef unsigned int u32;

#define IMG_W 2048
#define IMG_H 2048
#define NWORDS 32               // 32 x u64 = 2048 bits per column
#define NPIX (IMG_W * IMG_H)
#define COFF 8                  // column padding: prefetch/edge stores stay in-bounds
#define NCOLS (IMG_W + 2 * COFF)

// Interleaved bit grids, column-major: elem (c, w) = {A, L} for 64 rows.
// d_AL: canonical row order. d_ALr: reversed rows (brevll + word swap).
__device__ ulonglong2 d_AL [NCOLS * NWORDS];
__device__ ulonglong2 d_ALr[NCOLS * NWORDS];
// Per-column cross-lane propagate masks (bit w = lane w fully propagates),
// for canonical / reversed orientations. Zero-padded (padding never voted).
__device__ u32 d_P [NCOLS];
__device__ u32 d_Pr[NCOLS];

// ---------------------------------------------------------------------------
// Fused: low/high outputs + bitpack {A = thin>=3, L = thin>=1}, both grids.
// 4 threads per column-word (16 rows each), partials combined via smem.
// ---------------------------------------------------------------------------
__global__ void k_prep(const float* __restrict__ thin, float* __restrict__ out) {
    __shared__ u32 sL[4][32], sA[4][32];
    int c = blockIdx.x * 32 + threadIdx.x;
    int w = blockIdx.y;
    int q = threadIdx.y;                       // quarter: rows 16q..16q+15
    u32 Lq = 0, Aq = 0;
    size_t base = (size_t)(w * 64 + q * 16) * IMG_W + c;
    #pragma unroll 16
    for (int b = 0; b < 16; ++b) {
        size_t idx = base + (size_t)b * IMG_W;
        float v = thin[idx];
        bool lo = (v >= 1.0f), hi = (v >= 3.0f);
        out[idx]        = lo ? v : 0.0f;   // low
        out[NPIX + idx] = hi ? v : 0.0f;   // high
        Lq |= ((u32)lo) << b;
        Aq |= ((u32)hi) << b;
    }
    sL[q][threadIdx.x] = Lq;
    sA[q][threadIdx.x] = Aq;
    __syncthreads();
    if (q == 0) {
        u64 L = (u64)(sL[0][threadIdx.x] | (sL[1][threadIdx.x] << 16))
              | ((u64)(sL[2][threadIdx.x] | (sL[3][threadIdx.x] << 16)) << 32);
        u64 A = (u64)(sA[0][threadIdx.x] | (sA[1][threadIdx.x] << 16))
              | ((u64)(sA[2][threadIdx.x] | (sA[3][threadIdx.x] << 16)) << 32);
        d_AL [(c + COFF) * NWORDS + w]        = make_ulonglong2(A, L);
        d_ALr[(c + COFF) * NWORDS + (31 - w)] = make_ulonglong2(__brevll(A), __brevll(L));
    }
}

// ---------------------------------------------------------------------------
// Precompute per-column propagate masks: P[c] bit w = ((L & INTM_w) == ~0).
// One warp per column (lane = word). Reversed-grid mask = brev32(P).
// ---------------------------------------------------------------------------
__global__ void k_pmask() {
    int col = blockIdx.x * 8 + (threadIdx.x >> 5);
    int w   = threadIdx.x & 31;
    u64 INTM = ~0ull;
    if (w == 0)  INTM &= ~1ull;
    if (w == 31) INTM &= 0x7fffffffffffffffull;
    u64 L = d_AL[(size_t)(col + COFF) * NWORDS + w].y;
    u32 P = __ballot_sync(0xffffffffu, (L & INTM) == ~0ull);
    if (w == 0) {
        d_P [col + COFF] = P;
        d_Pr[col + COFF] = __brev(P);
    }
}

// ---------------------------------------------------------------------------
// One directional trace pass, single warp, software-pipelined by half a step.
// Gated-or scan s_i = g_i | (p_i & s_{i-1}) == carry chain of p+g (g subset p).
// Cross-lane: ONE ballot (BG = lane generates); propagate mask Pc comes from
// the precomputed per-column array. G,P disjoint => carry word
//   C = (Pc + (BG<<1)) ^ Pc     (== (BGP+BG)^(BGP^BG) of the 2-ballot form)
// bit k = cin of lane k, bit k+1 = cout of lane k.
// dn == cb; mid = cb|cb>>2|hi; side = mid|cb>>1|hi (hi-word fixups 32-bit).
// CROSS: stores go to the OTHER grid, word 31-lane, brevll'd (off-chain).
// ---------------------------------------------------------------------------
template <bool XR, bool CROSS>
__device__ __forceinline__ void trace_pass(const int lane,
                                           const ulonglong2* __restrict__ ldg,
                                           ulonglong2* __restrict__ stg,
                                           const u32* __restrict__ Pb) {
    const u32 FULL = 0xffffffffu;
    u64 INTM = ~0ull;
    if (lane == 0)  INTM &= ~1ull;                   // virtual row 0
    if (lane == 31) INTM &= 0x7fffffffffffffffull;   // virtual row 2047
    const u32 notTop1 = (lane == 31) ? 0u : 1u;

    const int dx  = XR ? -1 : 1;
    const int dxs = XR ? -NWORDS : NWORDS;           // column stride in ulonglong2
    const int cx0 = XR ? (IMG_W - 2) : 1;

    const ulonglong2* lbase = ldg + lane;
    ulonglong2 v;
    // shifted-by-one state: at start of iter j, Ap=col j-2, Ac=col j-1, An=col j
    v = lbase[(size_t)(cx0 - 2 * dx + COFF) * NWORDS];   // col -2 (padding)
    u64 Ap = v.x, Lp = v.y;
    v = lbase[(size_t)(cx0 - dx + COFF) * NWORDS];       // col -1 (boundary)
    u64 Ac = v.x, Lc = v.y;
    v = lbase[(size_t)(cx0 + COFF) * NWORDS];            // col 0
    u64 An = v.x, Ln = v.y;
    u64 gc = An & INTM, pc = Ln & INTM;                  // scan input, col 0
    u32 Pc = Pb[cx0 + COFF];                             // propagate mask, col 0
    u64 AnM = 0, LnM = 0;                                // set in iter 0
    u64 rA[6], rL[6];
    u32 rP[6];
    #pragma unroll
    for (int j = 0; j < 6; ++j) {                        // ring: cols 1..6
        v = lbase[(size_t)(cx0 + (1 + j) * dx + COFF) * NWORDS];
        rA[j] = v.x; rL[j] = v.y;
        rP[j] = Pb[cx0 + (1 + j) * dx + COFF];
    }
    const ulonglong2* ldp = lbase + (size_t)(cx0 + 7 * dx + COFF) * NWORDS;
    const u32* Pld = Pb + (cx0 + 7 * dx + COFF);
    u64* stp = (u64*)(stg + (size_t)(cx0 - 2 * dx + COFF) * NWORDS
                      + (CROSS ? (31 - lane) : lane));
    u64 side = 0, mid = 0;                               // of col j-1 (none yet)

    #pragma unroll 1
    for (int blk = 0; blk < (IMG_W - 2) / 6; ++blk) {    // 341 x 6 = 2046 iters
        #pragma unroll
        for (int j = 0; j < 6; ++j) {
            // ---- minimal pre-vote segment (column j) ----
            u64 sum0 = pc + gc;
            u64 sum1 = sum0 + 1;
            u32 BG  = __ballot_sync(FULL, sum0 < pc);    // lane generates
            u32 b0  = ((u32)gc & 1u) | (((u32)pc << 1) & 2u);
            u32 b0n = __shfl_down_sync(FULL, b0, 1);     // 26-cy latency hidden
            // ---- vote-flight fill: prefetch + speculative carry words ----
            ulonglong2 pf = ldp[j * dxs];                // prefetch col j+7
            u32 Pf = Pld[j * dx];                        // prefetch P, col j+7
            u64 cb0 = sum0 ^ pc ^ gc;                    // speculative cin=0
            u64 cb1 = sum1 ^ pc ^ gc;                    // speculative cin=1
            // ---- resolve col j, store-side (old side/mid) threaded between ----
            u32 C  = (Pc + (BG << 1)) ^ Pc;     // cin per lane; bit k+1 = cout k
            u64 stv = Ap | (side & Lp);                  // fill: final, col j-2
            u32 Cs = C >> lane;                 // bit0 = cin, bit1 = cout
            stp[2 * j * dxs] = CROSS ? __brevll(stv) : stv;   // fill: STG
            u64 cb = (Cs & 1u) ? cb1 : cb0;     // carry-in bit word == dn
            Ap = Ac | (mid & Lc);  Lp = Lc;              // fill: col j-1 acc
            u32 co = Cs & 2u;
            u32 s0n = (b0n | ((b0n >> 1) & (Cs >> 1))) & notTop1;
            Ac = An | (side & Ln); Lc = Ln;              // fill: col j acc
            u32 hm = (co << 29) | (s0n << 31);  // cout->bit62, s0n->bit63
            u32 hs = hm | (co << 30);           // + cout->bit63
            An = rA[j]; Ln = rL[j];                      // fill: ring rotate
            u64 t  = cb | (cb >> 2);
            rA[j] = pf.x; rL[j] = pf.y;                  // fill: ring store
            u32 Pnx = rP[j]; rP[j] = Pf;                 // fill: P ring rotate
            mid  = t | ((u64)hm << 32);
            AnM = An & INTM; LnM = Ln & INTM;            // fill: masked copies
            side = t | (cb >> 1) | ((u64)hs << 32);
            // ---- tail: scan input for column j+1 ----
            gc = AnM | (side & LnM);            // == (An|side&Ln) & INTM
            pc = LnM;
            Pc = Pnx;
        }
        ldp += 6 * dxs;
        Pld += 6 * dx;
        stp += 12 * dxs;
    }
    // epilogue: one final fill with the last side/mid, then flush
    u64 stv = Ap | (side & Lp);                          // col 2044
    stp[0] = CROSS ? __brevll(stv) : stv;
    Ap = Ac | (mid & Lc);                                // col 2045 final
    Ac = An | (side & Ln);                               // col 2046 final
    stp[2 * dxs] = CROSS ? __brevll(Ap) : Ap;
    stp[4 * dxs] = CROSS ? __brevll(Ac) : Ac;
}

__global__ void __launch_bounds__(32, 1) k_trace() {
    const int lane = threadIdx.x;
    // p1 (F,F): read AL,  write ALr (cross)
    trace_pass<false, true >(lane, d_AL,  d_ALr, d_P);
    __threadfence_block(); __syncwarp();
    // p2 (T,T): read/write ALr
    trace_pass<true,  false>(lane, d_ALr, d_ALr, d_Pr);
    __threadfence_block(); __syncwarp();
    // p3 (F,T): read ALr, write AL (cross)
    trace_pass<false, true >(lane, d_ALr, d_AL, d_Pr);
    __threadfence_block(); __syncwarp();
    // p4 (T,F): read/write AL
    trace_pass<true,  false>(lane, d_AL,  d_AL, d_P);
}

// ---------------------------------------------------------------------------
// final = A ? thin : 0. Tile 64 rows x 32 cols; 512 threads/block, 4 px each.
// ---------------------------------------------------------------------------
__global__ void k_final(const float* __restrict__ thin, float* __restrict__ out) {
    int c0 = blockIdx.x * 32;
    int r0 = blockIdx.y * 64;
    int lane = threadIdx.x & 31;
    int sub  = threadIdx.x >> 5;      // 0..15
    u64 wrd = d_AL[(c0 + lane + COFF) * NWORDS + (r0 >> 6)].x;
    #pragma unroll
    for (int k = 0; k < 4; ++k) {
        int rr = sub * 4 + k;
        size_t idx = (size_t)(r0 + rr) * IMG_W + c0 + lane;
        bool act = (wrd >> rr) & 1ull;
        out[2 * NPIX + idx] = act ? thin[idx] : 0.0f;
    }
}

// ---------------------------------------------------------------------------
extern "C" void kernel_launch(void* const* d_in, const int* in_sizes, int n_in,
                              void* d_out, int out_size) {
    const float* thin = (const float*)d_in[0];
    float* out = (float*)d_out;

    dim3 ppB(32, 4);                        // 128 thr: 32 cols x 4 quarters
    dim3 ppG(IMG_W / 32, NWORDS);           // 2048 blocks
    k_prep<<<ppG, ppB>>>(thin, out);

    k_pmask<<<IMG_W / 8, 256>>>();          // per-column propagate masks

    k_trace<<<1, 32>>>();

    dim3 fG(IMG_W / 32, IMG_H / 64);
    k_final<<<fG, 512>>>(thin, out);
}

// round 16
// speedup vs baseline: 1.0979x; 1.0979x over previous
#include <cuda_runtime.h>

typedef unsigned long long u64;
typedef unsigned int u32;

#define IMG_W 2048
#define IMG_H 2048
#define NWORDS 32               // 32 x u64 = 2048 bits per column
#define NPIX (IMG_W * IMG_H)
#define COFF 8                  // column padding: prefetch/edge stores stay in-bounds
#define NCOLS (IMG_W + 2 * COFF)

// Interleaved bit grids, column-major: elem (c, w) = {A, L} for 64 rows.
// d_AL: canonical row order. d_ALr: reversed rows (brevll + word swap).
// NOT pre-masked: boundary rows carry data (they receive smear writes).
__device__ ulonglong2 d_AL [NCOLS * NWORDS];
__device__ ulonglong2 d_ALr[NCOLS * NWORDS];

// ---------------------------------------------------------------------------
// Fused: low/high outputs + bitpack {A = thin>=3, L = thin>=1}, both grids.
// 8 threads per column-word (8 rows each), partials combined via smem.
// ---------------------------------------------------------------------------
__global__ void k_prep(const float* __restrict__ thin, float* __restrict__ out) {
    __shared__ u32 sL[8][32], sA[8][32];     // 8-bit partials in low byte
    int c = blockIdx.x * 32 + threadIdx.x;
    int w = blockIdx.y;
    int q = threadIdx.y;                     // eighth: rows 8q..8q+7
    u32 Lq = 0, Aq = 0;
    size_t base = (size_t)(w * 64 + q * 8) * IMG_W + c;
    #pragma unroll 8
    for (int b = 0; b < 8; ++b) {
        size_t idx = base + (size_t)b * IMG_W;
        float v = thin[idx];
        bool lo = (v >= 1.0f), hi = (v >= 3.0f);
        out[idx]        = lo ? v : 0.0f;   // low
        out[NPIX + idx] = hi ? v : 0.0f;   // high
        Lq |= ((u32)lo) << b;
        Aq |= ((u32)hi) << b;
    }
    sL[q][threadIdx.x] = Lq;
    sA[q][threadIdx.x] = Aq;
    __syncthreads();
    if (q == 0) {
        u32 llo = sL[0][threadIdx.x] | (sL[1][threadIdx.x] << 8)
                | (sL[2][threadIdx.x] << 16) | (sL[3][threadIdx.x] << 24);
        u32 lhi = sL[4][threadIdx.x] | (sL[5][threadIdx.x] << 8)
                | (sL[6][threadIdx.x] << 16) | (sL[7][threadIdx.x] << 24);
        u32 alo = sA[0][threadIdx.x] | (sA[1][threadIdx.x] << 8)
                | (sA[2][threadIdx.x] << 16) | (sA[3][threadIdx.x] << 24);
        u32 ahi = sA[4][threadIdx.x] | (sA[5][threadIdx.x] << 8)
                | (sA[6][threadIdx.x] << 16) | (sA[7][threadIdx.x] << 24);
        u64 L = (u64)llo | ((u64)lhi << 32);
        u64 A = (u64)alo | ((u64)ahi << 32);
        d_AL [(c + COFF) * NWORDS + w]        = make_ulonglong2(A, L);
        d_ALr[(c + COFF) * NWORDS + (31 - w)] = make_ulonglong2(__brevll(A), __brevll(L));
    }
}

// ---------------------------------------------------------------------------
// One directional trace pass, single warp, software-pipelined by half a step.
// Fill rebalanced: prefetch + cb-speculation cover the vote flight; the
// store-side block (depends only on OLD side) is threaded through the
// post-vote resolve chain to plug its latency bubbles.
// Gated-or scan s_i = g_i | (p_i & s_{i-1}) == carry chain of p+g (g subset p).
// Cross-lane carries: ballot BG = gen, BGP = gen|prop (pred: sum1 <= pc);
// C = (BGP+BG) ^ BGP ^ BG: bit k = cin of lane k, bit k+1 = cout of lane k.
// dn == cb; mid = cb|cb>>2|hi; side = mid|cb>>1|hi (hi-word fixups 32-bit).
// CROSS: stores go to the OTHER grid, word 31-lane, brevll'd (off-chain).
// ---------------------------------------------------------------------------
template <bool XR, bool CROSS>
__device__ __forceinline__ void trace_pass(const int lane,
                                           const ulonglong2* __restrict__ ldg,
                                           ulonglong2* __restrict__ stg) {
    const u32 FULL = 0xffffffffu;
    u64 INTM = ~0ull;
    if (lane == 0)  INTM &= ~1ull;                   // virtual row 0
    if (lane == 31) INTM &= 0x7fffffffffffffffull;   // virtual row 2047
    const u32 notTop1 = (lane == 31) ? 0u : 1u;

    const int dx  = XR ? -1 : 1;
    const int dxs = XR ? -NWORDS : NWORDS;           // column stride in ulonglong2
    const int cx0 = XR ? (IMG_W - 2) : 1;

    const ulonglong2* lbase = ldg + lane;
    ulonglong2 v;
    // shifted-by-one state: at start of iter j, Ap=col j-2, Ac=col j-1, An=col j
    v = lbase[(size_t)(cx0 - 2 * dx + COFF) * NWORDS];   // col -2 (padding)
    u64 Ap = v.x, Lp = v.y;
    v = lbase[(size_t)(cx0 - dx + COFF) * NWORDS];       // col -1 (boundary)
    u64 Ac = v.x, Lc = v.y;
    v = lbase[(size_t)(cx0 + COFF) * NWORDS];            // col 0
    u64 An = v.x, Ln = v.y;
    u64 gc = An & INTM, pc = Ln & INTM;                  // scan input, col 0
    u64 AnM = 0, LnM = 0;                                // set in iter 0
    u64 rA[6], rL[6];
    #pragma unroll
    for (int j = 0; j < 6; ++j) {                        // ring: cols 1..6
        v = lbase[(size_t)(cx0 + (1 + j) * dx + COFF) * NWORDS];
        rA[j] = v.x; rL[j] = v.y;
    }
    const ulonglong2* ldp = lbase + (size_t)(cx0 + 7 * dx + COFF) * NWORDS;
    u64* stp = (u64*)(stg + (size_t)(cx0 - 2 * dx + COFF) * NWORDS
                      + (CROSS ? (31 - lane) : lane));
    u64 side = 0, mid = 0;                               // of col j-1 (none yet)

    #pragma unroll 1
    for (int blk = 0; blk < (IMG_W - 2) / 6; ++blk) {    // 341 x 6 = 2046 iters
        #pragma unroll
        for (int j = 0; j < 6; ++j) {
            // ---- minimal pre-vote segment (column j) ----
            u64 sum0 = pc + gc;
            u64 sum1 = sum0 + 1;
            u32 BG  = __ballot_sync(FULL, sum0 < pc);    // lane generates
            u32 BGP = __ballot_sync(FULL, sum1 <= pc);   // generates OR propagates
            u32 b0  = ((u32)gc & 1u) | (((u32)pc << 1) & 2u);
            u32 b0n = __shfl_down_sync(FULL, b0, 1);     // 26-cy latency hidden
            // ---- vote-flight fill: prefetch + speculative carry words ----
            ulonglong2 pf = ldp[j * dxs];                // prefetch col j+7
            u64 cb0 = sum0 ^ pc ^ gc;                    // speculative cin=0
            u64 cb1 = sum1 ^ pc ^ gc;                    // speculative cin=1
            // ---- resolve col j, store-side (old side/mid) threaded between ----
            u32 C  = (BGP + BG) ^ BGP ^ BG;     // cin per lane; bit k+1 = cout k
            u64 stv = Ap | (side & Lp);                  // fill: final, col j-2
            u32 Cs = C >> lane;                 // bit0 = cin, bit1 = cout
            stp[2 * j * dxs] = CROSS ? __brevll(stv) : stv;   // fill: STG
            u64 cb = (Cs & 1u) ? cb1 : cb0;     // carry-in bit word == dn
            Ap = Ac | (mid & Lc);  Lp = Lc;              // fill: col j-1 acc
            u32 co = Cs & 2u;
            u32 s0n = (b0n | ((b0n >> 1) & (Cs >> 1))) & notTop1;
            Ac = An | (side & Ln); Lc = Ln;              // fill: col j acc
            u32 hm = (co << 29) | (s0n << 31);  // cout->bit62, s0n->bit63
            u32 hs = hm | (co << 30);           // + cout->bit63
            An = rA[j]; Ln = rL[j];                      // fill: ring rotate
            u64 t  = cb | (cb >> 2);
            rA[j] = pf.x; rL[j] = pf.y;                  // fill: ring store
            mid  = t | ((u64)hm << 32);
            AnM = An & INTM; LnM = Ln & INTM;            // fill: masked copies
            side = t | (cb >> 1) | ((u64)hs << 32);
            // ---- tail: scan input for column j+1 ----
            gc = AnM | (side & LnM);            // == (An|side&Ln) & INTM
            pc = LnM;
        }
        ldp += 6 * dxs;
        stp += 12 * dxs;
    }
    // epilogue: one final fill with the last side/mid, then flush
    u64 stv = Ap | (side & Lp);                          // col 2044
    stp[0] = CROSS ? __brevll(stv) : stv;
    Ap = Ac | (mid & Lc);                                // col 2045 final
    Ac = An | (side & Ln);                               // col 2046 final
    stp[2 * dxs] = CROSS ? __brevll(Ap) : Ap;
    stp[4 * dxs] = CROSS ? __brevll(Ac) : Ac;
}

__global__ void __launch_bounds__(32, 1) k_trace() {
    const int lane = threadIdx.x;
    // p1 (F,F): read AL,  write ALr (cross)
    trace_pass<false, true >(lane, d_AL,  d_ALr);
    __threadfence_block(); __syncwarp();
    // p2 (T,T): read/write ALr
    trace_pass<true,  false>(lane, d_ALr, d_ALr);
    __threadfence_block(); __syncwarp();
    // p3 (F,T): read ALr, write AL (cross)
    trace_pass<false, true >(lane, d_ALr, d_AL);
    __threadfence_block(); __syncwarp();
    // p4 (T,F): read/write AL
    trace_pass<true,  false>(lane, d_AL,  d_AL);
}

// ---------------------------------------------------------------------------
// final = A ? thin : 0. Tile 64 rows x 32 cols; 1024 threads/block, 2 px each.
// ---------------------------------------------------------------------------
__global__ void k_final(const float* __restrict__ thin, float* __restrict__ out) {
    int c0 = blockIdx.x * 32;
    int r0 = blockIdx.y * 64;
    int lane = threadIdx.x & 31;
    int sub  = threadIdx.x >> 5;      // 0..31
    u64 wrd = d_AL[(c0 + lane + COFF) * NWORDS + (r0 >> 6)].x;
    #pragma unroll
    for (int k = 0; k < 2; ++k) {
        int rr = sub * 2 + k;
        size_t idx = (size_t)(r0 + rr) * IMG_W + c0 + lane;
        bool act = (wrd >> rr) & 1ull;
        out[2 * NPIX + idx] = act ? thin[idx] : 0.0f;
    }
}

// ---------------------------------------------------------------------------
extern "C" void kernel_launch(void* const* d_in, const int* in_sizes, int n_in,
                              void* d_out, int out_size) {
    const float* thin = (const float*)d_in[0];
    float* out = (float*)d_out;

    dim3 ppB(32, 8);                        // 256 thr: 32 cols x 8 eighths
    dim3 ppG(IMG_W / 32, NWORDS);           // 2048 blocks
    k_prep<<<ppG, ppB>>>(thin, out);

    k_trace<<<1, 32>>>();

    dim3 fG(IMG_W / 32, IMG_H / 64);
    k_final<<<fG, 1024>>>(thin, out);
}

// round 17
// speedup vs baseline: 1.2271x; 1.1176x over previous
#include <cuda_runtime.h>

typedef unsigned long long u64;
typedef unsigned int u32;

#define IMG_W 2048
#define IMG_H 2048
#define NWORDS 32               // 32 x u64 = 2048 bits per column
#define NPIX (IMG_W * IMG_H)
#define COFF 16                 // column padding: deep prefetch stays in-bounds
#define NCOLS (IMG_W + 2 * COFF)
#define UNR 11                  // 2046 = 11 * 186
#define NBLK 186

// Interleaved bit grids, column-major: elem (c, w) = {A, L} for 64 rows.
// d_AL: canonical row order. d_ALr: reversed rows (brevll + word swap).
// NOT pre-masked: boundary rows carry data (they receive smear writes).
__device__ ulonglong2 d_AL [NCOLS * NWORDS];
__device__ ulonglong2 d_ALr[NCOLS * NWORDS];

// ---------------------------------------------------------------------------
// Fused: low/high outputs + bitpack {A = thin>=3, L = thin>=1}, both grids.
// 8 threads per column-word (8 rows each), partials combined via smem.
// ---------------------------------------------------------------------------
__global__ void k_prep(const float* __restrict__ thin, float* __restrict__ out) {
    __shared__ u32 sL[8][32], sA[8][32];     // 8-bit partials in low byte
    int c = blockIdx.x * 32 + threadIdx.x;
    int w = blockIdx.y;
    int q = threadIdx.y;                     // eighth: rows 8q..8q+7
    u32 Lq = 0, Aq = 0;
    size_t base = (size_t)(w * 64 + q * 8) * IMG_W + c;
    #pragma unroll 8
    for (int b = 0; b < 8; ++b) {
        size_t idx = base + (size_t)b * IMG_W;
        float v = thin[idx];
        bool lo = (v >= 1.0f), hi = (v >= 3.0f);
        out[idx]        = lo ? v : 0.0f;   // low
        out[NPIX + idx] = hi ? v : 0.0f;   // high
        Lq |= ((u32)lo) << b;
        Aq |= ((u32)hi) << b;
    }
    sL[q][threadIdx.x] = Lq;
    sA[q][threadIdx.x] = Aq;
    __syncthreads();
    if (q == 0) {
        u32 llo = sL[0][threadIdx.x] | (sL[1][threadIdx.x] << 8)
                | (sL[2][threadIdx.x] << 16) | (sL[3][threadIdx.x] << 24);
        u32 lhi = sL[4][threadIdx.x] | (sL[5][threadIdx.x] << 8)
                | (sL[6][threadIdx.x] << 16) | (sL[7][threadIdx.x] << 24);
        u32 alo = sA[0][threadIdx.x] | (sA[1][threadIdx.x] << 8)
                | (sA[2][threadIdx.x] << 16) | (sA[3][threadIdx.x] << 24);
        u32 ahi = sA[4][threadIdx.x] | (sA[5][threadIdx.x] << 8)
                | (sA[6][threadIdx.x] << 16) | (sA[7][threadIdx.x] << 24);
        u64 L = (u64)llo | ((u64)lhi << 32);
        u64 A = (u64)alo | ((u64)ahi << 32);
        d_AL [(c + COFF) * NWORDS + w]        = make_ulonglong2(A, L);
        d_ALr[(c + COFF) * NWORDS + (31 - w)] = make_ulonglong2(__brevll(A), __brevll(L));
    }
}

// ---------------------------------------------------------------------------
// One directional trace pass, single warp, software-pipelined by half a step.
// Fill rebalanced: prefetch + cb-speculation cover the vote flight; the
// store-side block (depends only on OLD side) is threaded through the
// post-vote resolve chain to plug its latency bubbles.
// Gated-or scan s_i = g_i | (p_i & s_{i-1}) == carry chain of p+g (g subset p).
// Cross-lane carries: ballot BG = gen, BGP = gen|prop (pred: sum1 <= pc);
// C = (BGP+BG) ^ BGP ^ BG: bit k = cin of lane k, bit k+1 = cout of lane k.
// dn == cb; mid = cb|cb>>2|hi; side = mid|cb>>1|hi (hi-word fixups 32-bit).
// CROSS: stores go to the OTHER grid, word 31-lane, brevll'd (off-chain).
// ---------------------------------------------------------------------------
template <bool XR, bool CROSS>
__device__ __forceinline__ void trace_pass(const int lane,
                                           const ulonglong2* __restrict__ ldg,
                                           ulonglong2* __restrict__ stg) {
    const u32 FULL = 0xffffffffu;
    u64 INTM = ~0ull;
    if (lane == 0)  INTM &= ~1ull;                   // virtual row 0
    if (lane == 31) INTM &= 0x7fffffffffffffffull;   // virtual row 2047
    const u32 notTop1 = (lane == 31) ? 0u : 1u;

    const int dx  = XR ? -1 : 1;
    const int dxs = XR ? -NWORDS : NWORDS;           // column stride in ulonglong2
    const int cx0 = XR ? (IMG_W - 2) : 1;

    const ulonglong2* lbase = ldg + lane;
    ulonglong2 v;
    // shifted-by-one state: at start of iter j, Ap=col j-2, Ac=col j-1, An=col j
    v = lbase[(size_t)(cx0 - 2 * dx + COFF) * NWORDS];   // col -2 (padding)
    u64 Ap = v.x, Lp = v.y;
    v = lbase[(size_t)(cx0 - dx + COFF) * NWORDS];       // col -1 (boundary)
    u64 Ac = v.x, Lc = v.y;
    v = lbase[(size_t)(cx0 + COFF) * NWORDS];            // col 0
    u64 An = v.x, Ln = v.y;
    u64 gc = An & INTM, pc = Ln & INTM;                  // scan input, col 0
    u64 AnM = 0, LnM = 0;                                // set in iter 0
    u64 rA[UNR], rL[UNR];
    #pragma unroll
    for (int j = 0; j < UNR; ++j) {                      // ring: cols 1..UNR
        v = lbase[(size_t)(cx0 + (1 + j) * dx + COFF) * NWORDS];
        rA[j] = v.x; rL[j] = v.y;
    }
    const ulonglong2* ldp = lbase + (size_t)(cx0 + (UNR + 1) * dx + COFF) * NWORDS;
    u64* stp = (u64*)(stg + (size_t)(cx0 - 2 * dx + COFF) * NWORDS
                      + (CROSS ? (31 - lane) : lane));
    u64 side = 0, mid = 0;                               // of col j-1 (none yet)

    #pragma unroll 1
    for (int blk = 0; blk < NBLK; ++blk) {               // 186 x 11 = 2046 iters
        #pragma unroll
        for (int j = 0; j < UNR; ++j) {
            // ---- minimal pre-vote segment (column j) ----
            u64 sum0 = pc + gc;
            u64 sum1 = sum0 + 1;
            u32 BG  = __ballot_sync(FULL, sum0 < pc);    // lane generates
            u32 BGP = __ballot_sync(FULL, sum1 <= pc);   // generates OR propagates
            u32 b0  = ((u32)gc & 1u) | (((u32)pc << 1) & 2u);
            u32 b0n = __shfl_down_sync(FULL, b0, 1);     // 26-cy latency hidden
            // ---- vote-flight fill: prefetch + speculative carry words ----
            ulonglong2 pf = ldp[j * dxs];                // prefetch col j+UNR+1
            u64 cb0 = sum0 ^ pc ^ gc;                    // speculative cin=0
            u64 cb1 = sum1 ^ pc ^ gc;                    // speculative cin=1
            // ---- resolve col j, store-side (old side/mid) threaded between ----
            u32 C  = (BGP + BG) ^ BGP ^ BG;     // cin per lane; bit k+1 = cout k
            u64 stv = Ap | (side & Lp);                  // fill: final, col j-2
            u32 Cs = C >> lane;                 // bit0 = cin, bit1 = cout
            stp[2 * j * dxs] = CROSS ? __brevll(stv) : stv;   // fill: STG
            u64 cb = (Cs & 1u) ? cb1 : cb0;     // carry-in bit word == dn
            Ap = Ac | (mid & Lc);  Lp = Lc;              // fill: col j-1 acc
            u32 co = Cs & 2u;
            u32 s0n = (b0n | ((b0n >> 1) & (Cs >> 1))) & notTop1;
            Ac = An | (side & Ln); Lc = Ln;              // fill: col j acc
            u32 hm = (co << 29) | (s0n << 31);  // cout->bit62, s0n->bit63
            u32 hs = hm | (co << 30);           // + cout->bit63
            An = rA[j]; Ln = rL[j];                      // fill: ring rotate
            u64 t  = cb | (cb >> 2);
            rA[j] = pf.x; rL[j] = pf.y;                  // fill: ring store
            mid  = t | ((u64)hm << 32);
            AnM = An & INTM; LnM = Ln & INTM;            // fill: masked copies
            side = t | (cb >> 1) | ((u64)hs << 32);
            // ---- tail: scan input for column j+1 ----
            gc = AnM | (side & LnM);            // == (An|side&Ln) & INTM
            pc = LnM;
        }
        ldp += UNR * dxs;
        stp += 2 * UNR * dxs;
    }
    // epilogue: one final fill with the last side/mid, then flush
    u64 stv = Ap | (side & Lp);                          // col 2044
    stp[0] = CROSS ? __brevll(stv) : stv;
    Ap = Ac | (mid & Lc);                                // col 2045 final
    Ac = An | (side & Ln);                               // col 2046 final
    stp[2 * dxs] = CROSS ? __brevll(Ap) : Ap;
    stp[4 * dxs] = CROSS ? __brevll(Ac) : Ac;
}

__global__ void __launch_bounds__(32, 1) k_trace() {
    const int lane = threadIdx.x;
    // p1 (F,F): read AL,  write ALr (cross)
    trace_pass<false, true >(lane, d_AL,  d_ALr);
    __threadfence_block(); __syncwarp();
    // p2 (T,T): read/write ALr
    trace_pass<true,  false>(lane, d_ALr, d_ALr);
    __threadfence_block(); __syncwarp();
    // p3 (F,T): read ALr, write AL (cross)
    trace_pass<false, true >(lane, d_ALr, d_AL);
    __threadfence_block(); __syncwarp();
    // p4 (T,F): read/write AL
    trace_pass<true,  false>(lane, d_AL,  d_AL);
}

// ---------------------------------------------------------------------------
// final = A ? thin : 0. Tile 64 rows x 32 cols; 1024 threads/block, 2 px each.
// ---------------------------------------------------------------------------
__global__ void k_final(const float* __restrict__ thin, float* __restrict__ out) {
    int c0 = blockIdx.x * 32;
    int r0 = blockIdx.y * 64;
    int lane = threadIdx.x & 31;
    int sub  = threadIdx.x >> 5;      // 0..31
    u64 wrd = d_AL[(c0 + lane + COFF) * NWORDS + (r0 >> 6)].x;
    #pragma unroll
    for (int k = 0; k < 2; ++k) {
        int rr = sub * 2 + k;
        size_t idx = (size_t)(r0 + rr) * IMG_W + c0 + lane;
        bool act = (wrd >> rr) & 1ull;
        out[2 * NPIX + idx] = act ? thin[idx] : 0.0f;
    }
}

// ---------------------------------------------------------------------------
extern "C" void kernel_launch(void* const* d_in, const int* in_sizes, int n_in,
                              void* d_out, int out_size) {
    const float* thin = (const float*)d_in[0];
    float* out = (float*)d_out;

    dim3 ppB(32, 8);                        // 256 thr: 32 cols x 8 eighths
    dim3 ppG(IMG_W / 32, NWORDS);           // 2048 blocks
    k_prep<<<ppG, ppB>>>(thin, out);

    k_trace<<<1, 32>>>();

    dim3 fG(IMG_W / 32, IMG_H / 64);
    k_final<<<fG, 1024>>>(thin, out);
}